// round 12
// baseline (speedup 1.0000x reference)
#include <cuda_runtime.h>
#include <cuda_fp16.h>
#include <math.h>
#include <stdint.h>

#define Bc 2
#define Nc 1024
#define Dc 512
#define Hc 8
#define DHc 64
#define HDc 512
#define FFc 2048
#define Mc (Bc*Nc)
#define BHc (Bc*Hc)
#define SCALEc 0.125f

// ---------------- device scratch ----------------------------------------------------
static __device__ __align__(256) __half g_xn[Mc*Dc];
static __device__ __align__(256) __half g_q[BHc*Nc*DHc];
static __device__ __align__(256) __half g_kw[4*BHc*2*Nc*DHc];  // per-layer [l][bh][2N][64]
static __device__ __align__(256) __half g_v[BHc*Nc*DHc];
static __device__ __align__(256) __half g_rcat[Mc*3*Dc];
static __device__ __align__(256) __half g_wall[3*Dc*4*HDc];
static __device__ __align__(256) float  g_wsall[Mc*4*HDc];
static __device__ __align__(256) __half g_sc[(size_t)BHc*Nc*2*Nc];   // fp16 scores
static __device__ __align__(256) __half g_attn[(size_t)BHc*Nc*Nc];
static __device__ __align__(256) __half g_av[Mc*HDc];
static __device__ __align__(256) __half g_h1[Mc*FFc];
static __device__ __align__(256) float  g_x[Mc*Dc];
static __device__ __align__(256) float  g_xmid[Mc*Dc];
static __device__ __align__(256) __half g_wqkvh[4*Dc*3*HDc];
static __device__ __align__(256) __half g_wouth[4*HDc*Dc];
static __device__ __align__(256) __half g_wff1h[4*Dc*FFc];
static __device__ __align__(256) __half g_wff2h[4*FFc*Dc];

// ---------------- asm helpers -------------------------------------------------------
__device__ __forceinline__ void mma16(float* c, const unsigned* a, const unsigned* b) {
    asm volatile("mma.sync.aligned.m16n8k16.row.col.f32.f16.f16.f32 "
        "{%0,%1,%2,%3}, {%4,%5,%6,%7}, {%8,%9}, {%0,%1,%2,%3};"
        : "+f"(c[0]), "+f"(c[1]), "+f"(c[2]), "+f"(c[3])
        : "r"(a[0]), "r"(a[1]), "r"(a[2]), "r"(a[3]), "r"(b[0]), "r"(b[1]));
}
__device__ __forceinline__ void ldm_x4(unsigned* r, unsigned addr) {
    asm volatile("ldmatrix.sync.aligned.m8n8.x4.shared.b16 {%0,%1,%2,%3}, [%4];"
        : "=r"(r[0]), "=r"(r[1]), "=r"(r[2]), "=r"(r[3]) : "r"(addr));
}
__device__ __forceinline__ void ldm_x2(unsigned* r, unsigned addr) {
    asm volatile("ldmatrix.sync.aligned.m8n8.x2.shared.b16 {%0,%1}, [%2];"
        : "=r"(r[0]), "=r"(r[1]) : "r"(addr));
}
__device__ __forceinline__ void ldm_x2t(unsigned* r, unsigned addr) {
    asm volatile("ldmatrix.sync.aligned.m8n8.x2.trans.shared.b16 {%0,%1}, [%2];"
        : "=r"(r[0]), "=r"(r[1]) : "r"(addr));
}
__device__ __forceinline__ void cp16s(unsigned dst, const void* src) {
    asm volatile("cp.async.cg.shared.global [%0], [%1], 16;\n" :: "r"(dst), "l"(src));
}
#define CP_COMMIT() asm volatile("cp.async.commit_group;\n" ::: "memory")
template<int N> __device__ __forceinline__ void cp_wait() {
    asm volatile("cp.async.wait_group %0;\n" :: "n"(N) : "memory");
}

__device__ __forceinline__ void stC(float* p, float v0, float v1) {
    *(float2*)p = make_float2(v0, v1);
}
__device__ __forceinline__ void stC(__half* p, float v0, float v1) {
    *(__half2*)p = __floats2half2_rn(v0, v1);
}

// ---------------- fp16 tensor-core GEMM (m16n8k16 + ldmatrix + cp.async xNS) --------
// C(MxN) = A(MxK) @ op(B).  TB=false: B KxN row-major; TB=true: B NxK row-major.
// mode: 0 plain, 1 +bias, 2 +bias+resid(f32), 3 +bias,gelu, 4 attn_v scatter,
//       5 qkv scatter: cols [0,512)->C(q,+bias_pf) [512,1024)->C2(kw) [1024,1536)->C3(v)
template<int BM, int BN, int WM, int WN, bool TB, typename CT, int NS>
__global__ __launch_bounds__(256, 2) void h_gemm(
    const __half* __restrict__ A, const __half* __restrict__ B, CT* __restrict__ C,
    int K, int lda, int ldb, int ldc,
    long long sA, long long sB, long long sC,
    const float* __restrict__ bias, const float* __restrict__ resid,
    CT* __restrict__ C2, CT* __restrict__ C3, int mode)
{
    constexpr int NWN = BN / WN;
    constexpr int MT = WM / 16;
    constexpr int NT = WN / 8;
    constexpr int IAc = (BM * 4) / 256;
    constexpr int IBc = (BN * 4) / 256;
    __shared__ __half As[NS][BM * 32];
    __shared__ __half Bs[NS][BN * 32];

    const __half* Ab = A + (size_t)sA * blockIdx.z;
    const __half* Bb = B + (size_t)sB * blockIdx.z;
    CT* Cb = C + (size_t)sC * blockIdx.z;

    int tid = threadIdx.x;
    int lane = tid & 31, wid = tid >> 5;
    int wm = (wid / NWN) * WM, wn = (wid % NWN) * WN;
    int gid = lane >> 2, tig = lane & 3;
    int bm0 = blockIdx.y * BM, bn0 = blockIdx.x * BN;

    unsigned sAs = (unsigned)__cvta_generic_to_shared(&As[0][0]);
    unsigned sBs = (unsigned)__cvta_generic_to_shared(&Bs[0][0]);

    float acc[MT][NT][4];
#pragma unroll
    for (int i = 0; i < MT; i++)
#pragma unroll
        for (int j = 0; j < NT; j++)
#pragma unroll
            for (int t = 0; t < 4; t++) acc[i][j][t] = 0.f;

    auto MOD = [](int x) { return ((NS & (NS - 1)) == 0) ? (x & (NS - 1)) : (x % NS); };

    auto COPY = [&](int st, int k0) {
#pragma unroll
        for (int it = 0; it < IAc; it++) {
            int ch = tid + it * 256;
            int m = ch >> 2, c = ch & 3;
            int cc = c ^ ((m >> 1) & 3);
            cp16s(sAs + (st * BM * 32 + m * 32 + cc * 8) * 2,
                  Ab + (size_t)(bm0 + m) * lda + k0 + c * 8);
        }
        if (TB) {
#pragma unroll
            for (int it = 0; it < IBc; it++) {
                int ch = tid + it * 256;
                int n = ch >> 2, c = ch & 3;
                int cc = c ^ ((n >> 1) & 3);
                cp16s(sBs + (st * BN * 32 + n * 32 + cc * 8) * 2,
                      Bb + (size_t)(bn0 + n) * ldb + k0 + c * 8);
            }
        } else {
#pragma unroll
            for (int it = 0; it < IBc; it++) {
                int ch = tid + it * 256;
                int k = ch / (BN / 8), nc = ch % (BN / 8);
                int cc = nc ^ (k & 7);
                cp16s(sBs + (st * BN * 32 + k * BN + cc * 8) * 2,
                      Bb + (size_t)(k0 + k) * ldb + bn0 + nc * 8);
            }
        }
    };
    auto MMASTEP = [&](int st, int s) {
        unsigned af[MT][4], bf[NT][2];
        unsigned abase = sAs + st * (BM * 32 * 2);
        unsigned bbase = sBs + st * (BN * 32 * 2);
        int la = lane & 7, t4 = lane >> 3;
#pragma unroll
        for (int mt = 0; mt < MT; mt++) {
            int m = wm + mt * 16 + (t4 & 1) * 8 + la;
            int c = 2 * s + (t4 >> 1);
            ldm_x4(af[mt], abase + (m * 32 + ((c ^ ((m >> 1) & 3)) << 3)) * 2);
        }
        if (TB) {
            int l2 = lane & 15;
#pragma unroll
            for (int nt = 0; nt < NT; nt++) {
                int n = wn + nt * 8 + (l2 & 7);
                int c = 2 * s + (l2 >> 3);
                ldm_x2(bf[nt], bbase + (n * 32 + ((c ^ ((n >> 1) & 3)) << 3)) * 2);
            }
        } else {
            int kk = 16 * s + (lane & 15);
#pragma unroll
            for (int nt = 0; nt < NT; nt++) {
                int nc = (wn + nt * 8) >> 3;
                ldm_x2t(bf[nt], bbase + (kk * BN + ((nc ^ (kk & 7)) << 3)) * 2);
            }
        }
#pragma unroll
        for (int mt = 0; mt < MT; mt++)
#pragma unroll
            for (int nt = 0; nt < NT; nt++)
                mma16(acc[mt][nt], af[mt], bf[nt]);
    };

    int nk = K >> 5;
#pragma unroll
    for (int s = 0; s < NS - 1; s++) {
        if (nk > s) COPY(s, s << 5);
        CP_COMMIT();
    }
    for (int kt = 0; kt < nk; kt++) {
        cp_wait<NS - 2>();
        __syncthreads();
        int nxt = kt + NS - 1;
        if (nxt < nk) COPY(MOD(nxt), nxt << 5);
        CP_COMMIT();
        int buf = MOD(kt);
        MMASTEP(buf, 0);
        MMASTEP(buf, 1);
    }

    // epilogue
#pragma unroll
    for (int mt = 0; mt < MT; mt++) {
        int r0 = bm0 + wm + mt * 16 + gid;
#pragma unroll
        for (int nt = 0; nt < NT; nt++) {
            int c0 = bn0 + wn + nt * 8 + tig * 2;
#pragma unroll
            for (int hf = 0; hf < 2; hf++) {
                int r = r0 + hf * 8;
                float v0 = acc[mt][nt][hf * 2 + 0];
                float v1 = acc[mt][nt][hf * 2 + 1];
                if (mode == 4) {
                    int bb2 = blockIdx.z >> 3, h = blockIdx.z & 7;
                    size_t off = ((size_t)(bb2 * Nc + r)) * HDc + h * DHc + c0;
                    stC(C + off, v0, v1);
                } else if (mode == 5) {
                    int seg = c0 >> 9, h = (c0 >> 6) & 7, d = c0 & 63;
                    int b = r >> 10, n = r & (Nc - 1);
                    int bh = b * Hc + h;
                    if (seg == 0) {
                        float2 bp = *(const float2*)(bias + h * DHc + d);
                        stC(C + ((size_t)(bh * Nc + n)) * DHc + d, v0 + bp.x, v1 + bp.y);
                    } else if (seg == 1) {
                        stC(C2 + ((size_t)bh * 2 * Nc + n) * DHc + d, v0, v1);
                    } else {
                        stC(C3 + ((size_t)(bh * Nc + n)) * DHc + d, v0, v1);
                    }
                } else {
                    size_t off = (size_t)r * ldc + c0;
                    if (mode == 1) { v0 += bias[c0]; v1 += bias[c0 + 1]; }
                    else if (mode == 2) {
                        float2 rr = *(const float2*)(resid + off);
                        v0 += bias[c0] + rr.x; v1 += bias[c0 + 1] + rr.y;
                    } else if (mode == 3) {
                        v0 += bias[c0]; v1 += bias[c0 + 1];
                        v0 = 0.5f * v0 * (1.f + erff(v0 * 0.70710678118654752f));
                        v1 = 0.5f * v1 * (1.f + erff(v1 * 0.70710678118654752f));
                    }
                    stC(Cb + off, v0, v1);
                }
            }
        }
    }
}

// ---------------- LayerNorm: f32 in -> half out -------------------------------------
__global__ __launch_bounds__(128) void ln_kernel(
    const float* __restrict__ in, __half* __restrict__ out,
    const float* __restrict__ g, const float* __restrict__ bta)
{
    int row = blockIdx.x;
    const float* xr = in + (size_t)row * Dc;
    __half* orow = out + (size_t)row * Dc;
    int tid = threadIdx.x;
    float4 v = *(const float4*)(xr + tid * 4);
    float s = v.x + v.y + v.z + v.w;
    float ss = v.x*v.x + v.y*v.y + v.z*v.z + v.w*v.w;
#pragma unroll
    for (int o = 16; o > 0; o >>= 1) {
        s  += __shfl_xor_sync(0xffffffffu, s, o);
        ss += __shfl_xor_sync(0xffffffffu, ss, o);
    }
    __shared__ float sh[8];
    int w = tid >> 5, lane = tid & 31;
    if (lane == 0) { sh[w] = s; sh[4+w] = ss; }
    __syncthreads();
    if (tid == 0) {
        sh[0] = sh[0]+sh[1]+sh[2]+sh[3];
        sh[1] = sh[4]+sh[5]+sh[6]+sh[7];
    }
    __syncthreads();
    float mean = sh[0] * (1.f/Dc);
    float var  = sh[1] * (1.f/Dc) - mean*mean;
    float inv  = rsqrtf(var + 1e-5f);
    int c = tid * 4;
    float4 gg = *(const float4*)(g + c);
    float4 bb = *(const float4*)(bta + c);
    float y0 = (v.x-mean)*inv*gg.x + bb.x;
    float y1 = (v.y-mean)*inv*gg.y + bb.y;
    float y2 = (v.z-mean)*inv*gg.z + bb.z;
    float y3 = (v.w-mean)*inv*gg.w + bb.w;
    ((__half2*)orow)[tid*2]   = __floats2half2_rn(y0, y1);
    ((__half2*)orow)[tid*2+1] = __floats2half2_rn(y2, y3);
}

// ---------------- all weights f32 -> half, single launch ----------------------------
__global__ void whall_kernel(
    const float* __restrict__ a, const float* __restrict__ b,
    const float* __restrict__ c, const float* __restrict__ d,
    __half* __restrict__ oa, __half* __restrict__ ob,
    __half* __restrict__ oc, __half* __restrict__ od)
{
    int i = blockIdx.x * blockDim.x + threadIdx.x;
    const int n1 = 4*Dc*3*HDc/4;
    const int n2 = n1 + 4*HDc*Dc/4;
    const int n3 = n2 + 4*Dc*FFc/4;
    const float* s; __half* o; int j;
    if (i < n1)      { s = a; o = oa; j = i; }
    else if (i < n2) { s = b; o = ob; j = i - n1; }
    else if (i < n3) { s = c; o = oc; j = i - n2; }
    else             { s = d; o = od; j = i - n3; }
    float4 t = ((const float4*)s)[j];
    ((__half2*)o)[j*2]   = __floats2half2_rn(t.x, t.y);
    ((__half2*)o)[j*2+1] = __floats2half2_rn(t.z, t.w);
}

// ---------------- build [r_t|r_c|r_p] half ------------------------------------------
__global__ void rcat_kernel(const float* __restrict__ rt, const float* __restrict__ rc,
                            const float* __restrict__ rp, __half* __restrict__ out)
{
    int idx = blockIdx.x * blockDim.x + threadIdx.x;
    int row = idx / 384, c4 = idx % 384;
    const float* srcs[3] = {rt, rc, rp};
    const float* s = srcs[c4 >> 7];
    int c = (c4 & 127) * 4;
    float4 t = *(const float4*)(s + (size_t)row*512 + c);
    ((__half2*)out)[idx*2]   = __floats2half2_rn(t.x, t.y);
    ((__half2*)out)[idx*2+1] = __floats2half2_rn(t.z, t.w);
}

// ---------------- build stacked W half (1536 x 2048) --------------------------------
__global__ void wall_kernel(const float* __restrict__ wkt, const float* __restrict__ wkc,
                            const float* __restrict__ wkp, __half* __restrict__ out)
{
    int idx = blockIdx.x * blockDim.x + threadIdx.x;
    int k = idx >> 9;
    int col4 = idx & 511;
    int l = col4 >> 7, c = (col4 & 127) * 4;
    const float* srcs[3] = {wkt, wkc, wkp};
    const float* s = srcs[k >> 9];
    int kk = k & 511;
    float4 t = *(const float4*)(s + ((size_t)l*512 + kk) * 512 + c);
    ((__half2*)out)[idx*2]   = __floats2half2_rn(t.x, t.y);
    ((__half2*)out)[idx*2+1] = __floats2half2_rn(t.z, t.w);
}

// ---------------- all-layers Wsr -> kw rows [1024,2048), /3 -------------------------
__global__ void wsr_all_kernel(const float* __restrict__ wsall, __half* __restrict__ kw)
{
    int idx = blockIdx.x * blockDim.x + threadIdx.x;  // 4*B*H*N*(DH/4)
    int d4 = idx & 15;
    int n = (idx >> 4) & (Nc - 1);
    int h = (idx >> 14) & 7;
    int b = (idx >> 17) & 1;
    int l = idx >> 18;
    int bh = b * Hc + h;
    float4 t = *(const float4*)(wsall + ((size_t)(b*Nc + n)) * 2048 + l*512 + h*64 + d4*4);
    size_t kd = ((size_t)l * BHc * 2 * Nc + (size_t)bh * 2 * Nc + Nc + n) * DHc + d4*4;
    ((__half2*)(kw + kd))[0] = __floats2half2_rn(t.x*(1.f/3.f), t.y*(1.f/3.f));
    ((__half2*)(kw + kd))[1] = __floats2half2_rn(t.z*(1.f/3.f), t.w*(1.f/3.f));
}

// ---------------- fused combine + rel_shift + softmax over heads (fp16 scores) ------
__global__ void softmax_fused_kernel(const __half* __restrict__ sc,
                                     __half* __restrict__ attn,
                                     float* __restrict__ attn_raw)
{
    int t = blockIdx.x * blockDim.x + threadIdx.x;   // B*N*(N/4)
    int j4 = (t & 255) * 4;
    int i = (t >> 8) & (Nc - 1);
    int b = t >> 18;
    size_t scb = ((size_t)(b * Hc)) << 21;           // bh stride = 1024*2048 = 2^21
    float d[Hc][4];
#pragma unroll
    for (int h = 0; h < Hc; h++) {
        const __half2* p = (const __half2*)(sc + scb + ((size_t)h << 21) + (size_t)i * 2048 + j4);
        float2 a0 = __half22float2(p[0]);
        float2 a1 = __half22float2(p[1]);
        d[h][0] = a0.x; d[h][1] = a0.y; d[h][2] = a1.x; d[h][3] = a1.y;
    }
#pragma unroll
    for (int e = 0; e < 4; e++) {
        int j = j4 + e;
        int f = i * Nc + j + Nc;
        int i2 = f / (Nc + 1);
        int jj = f - i2 * (Nc + 1);
        if (jj != 0) {
            size_t bd = scb + (size_t)i2 * 2048 + Nc + (jj - 1);
#pragma unroll
            for (int h = 0; h < Hc; h++)
                d[h][e] = (d[h][e] + __half2float(sc[bd + ((size_t)h << 21)])) * SCALEc;
        } else {
#pragma unroll
            for (int h = 0; h < Hc; h++) d[h][e] *= SCALEc;
        }
    }
#pragma unroll
    for (int e = 0; e < 4; e++) {
        float m = d[0][e];
#pragma unroll
        for (int h = 1; h < Hc; h++) m = fmaxf(m, d[h][e]);
        float s = 0.f;
#pragma unroll
        for (int h = 0; h < Hc; h++) { d[h][e] = expf(d[h][e] - m); s += d[h][e]; }
        float inv = 1.f / s;
#pragma unroll
        for (int h = 0; h < Hc; h++) d[h][e] *= inv;
    }
    size_t abase = (((size_t)(b * Hc)) << 20) + (size_t)i * Nc + j4;
#pragma unroll
    for (int h = 0; h < Hc; h++) {
        size_t o = abase + ((size_t)h << 20);
        if (attn_raw) {
            float4 r; r.x = d[h][0]; r.y = d[h][1]; r.z = d[h][2]; r.w = d[h][3];
            *(float4*)(attn_raw + o) = r;
        }
        ((__half2*)(attn + o))[0] = __floats2half2_rn(d[h][0], d[h][1]);
        ((__half2*)(attn + o))[1] = __floats2half2_rn(d[h][2], d[h][3]);
    }
}

// ===================================================================================
extern "C" void kernel_launch(void* const* d_in, const int* in_sizes, int n_in,
                              void* d_out, int out_size)
{
    const float* x_in    = (const float*)d_in[0];
    const float* r_t     = (const float*)d_in[1];
    const float* r_c     = (const float*)d_in[2];
    const float* r_p     = (const float*)d_in[3];
    const float* bias_pf = (const float*)d_in[4];
    const float* ln1_g   = (const float*)d_in[5];
    const float* ln1_b   = (const float*)d_in[6];
    const float* w_qkv   = (const float*)d_in[7];
    const float* w_out   = (const float*)d_in[8];
    const float* b_out   = (const float*)d_in[9];
    const float* w_kt    = (const float*)d_in[10];
    const float* w_kc    = (const float*)d_in[11];
    const float* w_kp    = (const float*)d_in[12];
    const float* ln2_g   = (const float*)d_in[13];
    const float* ln2_b   = (const float*)d_in[14];
    const float* w_ff1   = (const float*)d_in[15];
    const float* b_ff1   = (const float*)d_in[16];
    const float* w_ff2   = (const float*)d_in[17];
    const float* b_ff2   = (const float*)d_in[18];
    float* out = (float*)d_out;

    __half *xn, *q, *kw, *v, *rcat, *wall, *sc, *attnb, *av, *h1,
           *wqkvh, *wouth, *wff1h, *wff2h;
    float *wsall, *x, *xmid;
    cudaGetSymbolAddress((void**)&xn, g_xn);
    cudaGetSymbolAddress((void**)&q, g_q);
    cudaGetSymbolAddress((void**)&kw, g_kw);
    cudaGetSymbolAddress((void**)&v, g_v);
    cudaGetSymbolAddress((void**)&rcat, g_rcat);
    cudaGetSymbolAddress((void**)&wall, g_wall);
    cudaGetSymbolAddress((void**)&wsall, g_wsall);
    cudaGetSymbolAddress((void**)&sc, g_sc);
    cudaGetSymbolAddress((void**)&attnb, g_attn);
    cudaGetSymbolAddress((void**)&av, g_av);
    cudaGetSymbolAddress((void**)&h1, g_h1);
    cudaGetSymbolAddress((void**)&x, g_x);
    cudaGetSymbolAddress((void**)&xmid, g_xmid);
    cudaGetSymbolAddress((void**)&wqkvh, g_wqkvh);
    cudaGetSymbolAddress((void**)&wouth, g_wouth);
    cudaGetSymbolAddress((void**)&wff1h, g_wff1h);
    cudaGetSymbolAddress((void**)&wff2h, g_wff2h);

    float* x_out    = out;
    float* attn_out = out + (size_t)Mc * Dc;

    // one-time stream/event setup (correctness call; reused under capture)
    static cudaStream_t s_side = nullptr;
    static cudaEvent_t ev_fork = nullptr, ev_join = nullptr;
    if (!s_side) {
        cudaStreamCreateWithFlags(&s_side, cudaStreamNonBlocking);
        cudaEventCreateWithFlags(&ev_fork, cudaEventDisableTiming);
        cudaEventCreateWithFlags(&ev_join, cudaEventDisableTiming);
    }

    // ---- fork: relative-projection chain on side stream ----------------------------
    cudaEventRecord(ev_fork, 0);
    cudaStreamWaitEvent(s_side, ev_fork, 0);
    rcat_kernel<<<(Mc*3*Dc/4)/256, 256, 0, s_side>>>(r_t, r_c, r_p, rcat);
    wall_kernel<<<(3*Dc*2048/4)/256, 256, 0, s_side>>>(w_kt, w_kc, w_kp, wall);
    h_gemm<128,128,64,32,false,float,3><<<dim3(16,16), 256, 0, s_side>>>(
        rcat, wall, wsall, 3*Dc, 3*Dc, 2048, 2048, 0,0,0,
        nullptr, nullptr, nullptr, nullptr, 0);
    wsr_all_kernel<<<(4*BHc*Nc*DHc/4)/256, 256, 0, s_side>>>(wsall, kw);
    cudaEventRecord(ev_join, s_side);

    // ---- main stream: weight conversion + layer-0 front ----------------------------
    whall_kernel<<<(4*Dc*3*HDc/4 + 4*HDc*Dc/4 + 4*Dc*FFc/4 + 4*FFc*Dc/4)/256, 256>>>(
        w_qkv, w_out, w_ff1, w_ff2, wqkvh, wouth, wff1h, wff2h);
    ln_kernel<<<Mc, 128>>>(x_in, xn, ln1_g, ln1_b);
    h_gemm<128,128,64,32,false,__half,3><<<dim3(12,16), 256>>>(
        xn, wqkvh, q /*C=q*/, Dc, Dc, 3*HDc, 3*HDc, 0,0,0,
        bias_pf, nullptr, kw /*C2: layer 0*/, v, 5);

    // join: scores need kw Wsr halves
    cudaStreamWaitEvent(0, ev_join, 0);

    const float* cur = x_in;
    for (int l = 0; l < 4; l++) {
        __half* kw_l = kw + (size_t)l * BHc * 2 * Nc * DHc;
        if (l > 0) {
            ln_kernel<<<Mc, 128>>>(cur, xn, ln1_g + l*Dc, ln1_b + l*Dc);
            h_gemm<128,128,64,32,false,__half,3><<<dim3(12,16), 256>>>(
                xn, wqkvh + (size_t)l*Dc*3*HDc, q, Dc, Dc, 3*HDc, 3*HDc, 0,0,0,
                bias_pf, nullptr, kw_l, v, 5);
        }
        // combined scores: [AC | BDraw] in one GEMM, N=2048 per bh, fp16 out
        h_gemm<128,128,64,32,true,__half,3><<<dim3(16,8,BHc), 256>>>(
            q, kw_l, sc, DHc, DHc, DHc, 2*Nc,
            (long long)Nc*DHc, (long long)2*Nc*DHc, (long long)Nc*2*Nc,
            nullptr, nullptr, nullptr, nullptr, 0);
        softmax_fused_kernel<<<(int)(((size_t)Bc*Nc*Nc/4)/256), 256>>>(
            sc, attnb, (l == 3) ? attn_out : nullptr);
        h_gemm<64,64,32,16,false,__half,4><<<dim3(1,16,BHc), 256>>>(
            attnb, v, av, Nc, Nc, DHc, HDc,
            (long long)Nc*Nc, (long long)Nc*DHc, 0,
            nullptr, nullptr, nullptr, nullptr, 4);
        h_gemm<64,64,32,16,false,float,4><<<dim3(8,32), 256>>>(
            av, wouth + (size_t)l*HDc*Dc, xmid, HDc, HDc, Dc, Dc,
            0,0,0, b_out + l*Dc, cur, nullptr, nullptr, 2);
        ln_kernel<<<Mc, 128>>>(xmid, xn, ln2_g + l*Dc, ln2_b + l*Dc);
        h_gemm<128,128,64,32,false,__half,3><<<dim3(16,16), 256>>>(
            xn, wff1h + (size_t)l*Dc*FFc, h1, Dc, Dc, FFc, FFc,
            0,0,0, b_ff1 + l*FFc, nullptr, nullptr, nullptr, 3);
        float* xdst = (l == 3) ? x_out : x;
        h_gemm<64,64,32,16,false,float,4><<<dim3(8,32), 256>>>(
            h1, wff2h + (size_t)l*FFc*Dc, xdst, FFc, FFc, Dc, Dc,
            0,0,0, b_ff2 + l*Dc, xmid, nullptr, nullptr, 2);
        cur = x;
    }
}

// round 16
// speedup vs baseline: 1.4431x; 1.4431x over previous
#include <cuda_runtime.h>
#include <cuda_fp16.h>
#include <math.h>
#include <stdint.h>

#define Bc 2
#define Nc 1024
#define Dc 512
#define Hc 8
#define DHc 64
#define HDc 512
#define FFc 2048
#define Mc (Bc*Nc)
#define BHc (Bc*Hc)
#define SCALEc 0.125f

// ---------------- device scratch ----------------------------------------------------
static __device__ __align__(256) __half g_xn[Mc*Dc];
static __device__ __align__(256) __half g_q[BHc*Nc*DHc];
static __device__ __align__(256) __half g_kw[4*BHc*2*Nc*DHc];  // per-layer [l][bh][2N][64]
static __device__ __align__(256) __half g_v[BHc*Nc*DHc];
static __device__ __align__(256) __half g_rcat[Mc*3*Dc];
static __device__ __align__(256) __half g_wall[3*Dc*4*HDc];
static __device__ __align__(256) float  g_wsall[Mc*4*HDc];
static __device__ __align__(256) __half g_sc[(size_t)BHc*Nc*2*Nc];   // fp16 scores
static __device__ __align__(256) __half g_attn[(size_t)BHc*Nc*Nc];
static __device__ __align__(256) __half g_av[Mc*HDc];
static __device__ __align__(256) __half g_h1[Mc*FFc];
static __device__ __align__(256) float  g_x[Mc*Dc];
static __device__ __align__(256) float  g_xmid[Mc*Dc];
static __device__ __align__(256) __half g_wqkvh[4*Dc*3*HDc];
static __device__ __align__(256) __half g_wouth[4*HDc*Dc];
static __device__ __align__(256) __half g_wff1h[4*Dc*FFc];
static __device__ __align__(256) __half g_wff2h[4*FFc*Dc];

// ---------------- asm helpers -------------------------------------------------------
__device__ __forceinline__ void mma16(float* c, const unsigned* a, const unsigned* b) {
    asm volatile("mma.sync.aligned.m16n8k16.row.col.f32.f16.f16.f32 "
        "{%0,%1,%2,%3}, {%4,%5,%6,%7}, {%8,%9}, {%0,%1,%2,%3};"
        : "+f"(c[0]), "+f"(c[1]), "+f"(c[2]), "+f"(c[3])
        : "r"(a[0]), "r"(a[1]), "r"(a[2]), "r"(a[3]), "r"(b[0]), "r"(b[1]));
}
__device__ __forceinline__ void ldm_x4(unsigned* r, unsigned addr) {
    asm volatile("ldmatrix.sync.aligned.m8n8.x4.shared.b16 {%0,%1,%2,%3}, [%4];"
        : "=r"(r[0]), "=r"(r[1]), "=r"(r[2]), "=r"(r[3]) : "r"(addr));
}
__device__ __forceinline__ void ldm_x2(unsigned* r, unsigned addr) {
    asm volatile("ldmatrix.sync.aligned.m8n8.x2.shared.b16 {%0,%1}, [%2];"
        : "=r"(r[0]), "=r"(r[1]) : "r"(addr));
}
__device__ __forceinline__ void ldm_x2t(unsigned* r, unsigned addr) {
    asm volatile("ldmatrix.sync.aligned.m8n8.x2.trans.shared.b16 {%0,%1}, [%2];"
        : "=r"(r[0]), "=r"(r[1]) : "r"(addr));
}
__device__ __forceinline__ void cp16s(unsigned dst, const void* src) {
    asm volatile("cp.async.cg.shared.global [%0], [%1], 16;\n" :: "r"(dst), "l"(src));
}
#define CP_COMMIT() asm volatile("cp.async.commit_group;\n" ::: "memory")
template<int N> __device__ __forceinline__ void cp_wait() {
    asm volatile("cp.async.wait_group %0;\n" :: "n"(N) : "memory");
}

__device__ __forceinline__ void stC(float* p, float v0, float v1) {
    *(float2*)p = make_float2(v0, v1);
}
__device__ __forceinline__ void stC(__half* p, float v0, float v1) {
    *(__half2*)p = __floats2half2_rn(v0, v1);
}

// ---------------- fp16 tensor-core GEMM (m16n8k16 + ldmatrix + cp.async xNS) --------
// C(MxN) = A(MxK) @ op(B).  TB=false: B KxN row-major; TB=true: B NxK row-major.
// mode: 0 plain, 1 +bias, 2 +bias+resid(f32), 3 +bias,gelu, 4 attn_v scatter,
//       5 qkv scatter: cols [0,512)->C(q,+bias_pf) [512,1024)->C2(kw) [1024,1536)->C3(v)
template<int BM, int BN, int WM, int WN, bool TB, typename CT, int NS>
__global__ __launch_bounds__(256, 2) void h_gemm(
    const __half* __restrict__ A, const __half* __restrict__ B, CT* __restrict__ C,
    int K, int lda, int ldb, int ldc,
    long long sA, long long sB, long long sC,
    const float* __restrict__ bias, const float* __restrict__ resid,
    CT* __restrict__ C2, CT* __restrict__ C3, int mode)
{
    constexpr int NWN = BN / WN;
    constexpr int MT = WM / 16;
    constexpr int NT = WN / 8;
    constexpr int IAc = (BM * 4) / 256;
    constexpr int IBc = (BN * 4) / 256;
    __shared__ __half As[NS][BM * 32];
    __shared__ __half Bs[NS][BN * 32];

    const __half* Ab = A + (size_t)sA * blockIdx.z;
    const __half* Bb = B + (size_t)sB * blockIdx.z;
    CT* Cb = C + (size_t)sC * blockIdx.z;

    int tid = threadIdx.x;
    int lane = tid & 31, wid = tid >> 5;
    int wm = (wid / NWN) * WM, wn = (wid % NWN) * WN;
    int gid = lane >> 2, tig = lane & 3;
    int bm0 = blockIdx.y * BM, bn0 = blockIdx.x * BN;

    unsigned sAs = (unsigned)__cvta_generic_to_shared(&As[0][0]);
    unsigned sBs = (unsigned)__cvta_generic_to_shared(&Bs[0][0]);

    float acc[MT][NT][4];
#pragma unroll
    for (int i = 0; i < MT; i++)
#pragma unroll
        for (int j = 0; j < NT; j++)
#pragma unroll
            for (int t = 0; t < 4; t++) acc[i][j][t] = 0.f;

    auto MOD = [](int x) { return ((NS & (NS - 1)) == 0) ? (x & (NS - 1)) : (x % NS); };

    auto COPY = [&](int st, int k0) {
#pragma unroll
        for (int it = 0; it < IAc; it++) {
            int ch = tid + it * 256;
            int m = ch >> 2, c = ch & 3;
            int cc = c ^ ((m >> 1) & 3);
            cp16s(sAs + (st * BM * 32 + m * 32 + cc * 8) * 2,
                  Ab + (size_t)(bm0 + m) * lda + k0 + c * 8);
        }
        if (TB) {
#pragma unroll
            for (int it = 0; it < IBc; it++) {
                int ch = tid + it * 256;
                int n = ch >> 2, c = ch & 3;
                int cc = c ^ ((n >> 1) & 3);
                cp16s(sBs + (st * BN * 32 + n * 32 + cc * 8) * 2,
                      Bb + (size_t)(bn0 + n) * ldb + k0 + c * 8);
            }
        } else {
#pragma unroll
            for (int it = 0; it < IBc; it++) {
                int ch = tid + it * 256;
                int k = ch / (BN / 8), nc = ch % (BN / 8);
                int cc = nc ^ (k & 7);
                cp16s(sBs + (st * BN * 32 + k * BN + cc * 8) * 2,
                      Bb + (size_t)(k0 + k) * ldb + bn0 + nc * 8);
            }
        }
    };
    auto MMASTEP = [&](int st, int s) {
        unsigned af[MT][4], bf[NT][2];
        unsigned abase = sAs + st * (BM * 32 * 2);
        unsigned bbase = sBs + st * (BN * 32 * 2);
        int la = lane & 7, t4 = lane >> 3;
#pragma unroll
        for (int mt = 0; mt < MT; mt++) {
            int m = wm + mt * 16 + (t4 & 1) * 8 + la;
            int c = 2 * s + (t4 >> 1);
            ldm_x4(af[mt], abase + (m * 32 + ((c ^ ((m >> 1) & 3)) << 3)) * 2);
        }
        if (TB) {
            int l2 = lane & 15;
#pragma unroll
            for (int nt = 0; nt < NT; nt++) {
                int n = wn + nt * 8 + (l2 & 7);
                int c = 2 * s + (l2 >> 3);
                ldm_x2(bf[nt], bbase + (n * 32 + ((c ^ ((n >> 1) & 3)) << 3)) * 2);
            }
        } else {
            int kk = 16 * s + (lane & 15);
#pragma unroll
            for (int nt = 0; nt < NT; nt++) {
                int nc = (wn + nt * 8) >> 3;
                ldm_x2t(bf[nt], bbase + (kk * BN + ((nc ^ (kk & 7)) << 3)) * 2);
            }
        }
#pragma unroll
        for (int mt = 0; mt < MT; mt++)
#pragma unroll
            for (int nt = 0; nt < NT; nt++)
                mma16(acc[mt][nt], af[mt], bf[nt]);
    };

    int nk = K >> 5;
#pragma unroll
    for (int s = 0; s < NS - 1; s++) {
        if (nk > s) COPY(s, s << 5);
        CP_COMMIT();
    }
    for (int kt = 0; kt < nk; kt++) {
        cp_wait<NS - 2>();
        __syncthreads();
        int nxt = kt + NS - 1;
        if (nxt < nk) COPY(MOD(nxt), nxt << 5);
        CP_COMMIT();
        int buf = MOD(kt);
        MMASTEP(buf, 0);
        MMASTEP(buf, 1);
    }

    // epilogue
#pragma unroll
    for (int mt = 0; mt < MT; mt++) {
        int r0 = bm0 + wm + mt * 16 + gid;
#pragma unroll
        for (int nt = 0; nt < NT; nt++) {
            int c0 = bn0 + wn + nt * 8 + tig * 2;
#pragma unroll
            for (int hf = 0; hf < 2; hf++) {
                int r = r0 + hf * 8;
                float v0 = acc[mt][nt][hf * 2 + 0];
                float v1 = acc[mt][nt][hf * 2 + 1];
                if (mode == 4) {
                    int bb2 = blockIdx.z >> 3, h = blockIdx.z & 7;
                    size_t off = ((size_t)(bb2 * Nc + r)) * HDc + h * DHc + c0;
                    stC(C + off, v0, v1);
                } else if (mode == 5) {
                    int seg = c0 >> 9, h = (c0 >> 6) & 7, d = c0 & 63;
                    int b = r >> 10, n = r & (Nc - 1);
                    int bh = b * Hc + h;
                    if (seg == 0) {
                        float2 bp = *(const float2*)(bias + h * DHc + d);
                        stC(C + ((size_t)(bh * Nc + n)) * DHc + d, v0 + bp.x, v1 + bp.y);
                    } else if (seg == 1) {
                        stC(C2 + ((size_t)bh * 2 * Nc + n) * DHc + d, v0, v1);
                    } else {
                        stC(C3 + ((size_t)(bh * Nc + n)) * DHc + d, v0, v1);
                    }
                } else {
                    size_t off = (size_t)r * ldc + c0;
                    if (mode == 1) { v0 += bias[c0]; v1 += bias[c0 + 1]; }
                    else if (mode == 2) {
                        float2 rr = *(const float2*)(resid + off);
                        v0 += bias[c0] + rr.x; v1 += bias[c0 + 1] + rr.y;
                    } else if (mode == 3) {
                        v0 += bias[c0]; v1 += bias[c0 + 1];
                        v0 = 0.5f * v0 * (1.f + erff(v0 * 0.70710678118654752f));
                        v1 = 0.5f * v1 * (1.f + erff(v1 * 0.70710678118654752f));
                    }
                    stC(Cb + off, v0, v1);
                }
            }
        }
    }
}

// ---------------- LayerNorm: f32 in -> half out -------------------------------------
__global__ __launch_bounds__(128) void ln_kernel(
    const float* __restrict__ in, __half* __restrict__ out,
    const float* __restrict__ g, const float* __restrict__ bta)
{
    int row = blockIdx.x;
    const float* xr = in + (size_t)row * Dc;
    __half* orow = out + (size_t)row * Dc;
    int tid = threadIdx.x;
    float4 v = *(const float4*)(xr + tid * 4);
    float s = v.x + v.y + v.z + v.w;
    float ss = v.x*v.x + v.y*v.y + v.z*v.z + v.w*v.w;
#pragma unroll
    for (int o = 16; o > 0; o >>= 1) {
        s  += __shfl_xor_sync(0xffffffffu, s, o);
        ss += __shfl_xor_sync(0xffffffffu, ss, o);
    }
    __shared__ float sh[8];
    int w = tid >> 5, lane = tid & 31;
    if (lane == 0) { sh[w] = s; sh[4+w] = ss; }
    __syncthreads();
    if (tid == 0) {
        sh[0] = sh[0]+sh[1]+sh[2]+sh[3];
        sh[1] = sh[4]+sh[5]+sh[6]+sh[7];
    }
    __syncthreads();
    float mean = sh[0] * (1.f/Dc);
    float var  = sh[1] * (1.f/Dc) - mean*mean;
    float inv  = rsqrtf(var + 1e-5f);
    int c = tid * 4;
    float4 gg = *(const float4*)(g + c);
    float4 bb = *(const float4*)(bta + c);
    float y0 = (v.x-mean)*inv*gg.x + bb.x;
    float y1 = (v.y-mean)*inv*gg.y + bb.y;
    float y2 = (v.z-mean)*inv*gg.z + bb.z;
    float y3 = (v.w-mean)*inv*gg.w + bb.w;
    ((__half2*)orow)[tid*2]   = __floats2half2_rn(y0, y1);
    ((__half2*)orow)[tid*2+1] = __floats2half2_rn(y2, y3);
}

// ---------------- all weights f32 -> half, single launch ----------------------------
__global__ void whall_kernel(
    const float* __restrict__ a, const float* __restrict__ b,
    const float* __restrict__ c, const float* __restrict__ d,
    __half* __restrict__ oa, __half* __restrict__ ob,
    __half* __restrict__ oc, __half* __restrict__ od)
{
    int i = blockIdx.x * blockDim.x + threadIdx.x;
    const int n1 = 4*Dc*3*HDc/4;
    const int n2 = n1 + 4*HDc*Dc/4;
    const int n3 = n2 + 4*Dc*FFc/4;
    const float* s; __half* o; int j;
    if (i < n1)      { s = a; o = oa; j = i; }
    else if (i < n2) { s = b; o = ob; j = i - n1; }
    else if (i < n3) { s = c; o = oc; j = i - n2; }
    else             { s = d; o = od; j = i - n3; }
    float4 t = ((const float4*)s)[j];
    ((__half2*)o)[j*2]   = __floats2half2_rn(t.x, t.y);
    ((__half2*)o)[j*2+1] = __floats2half2_rn(t.z, t.w);
}

// ---------------- build [r_t|r_c|r_p] half ------------------------------------------
__global__ void rcat_kernel(const float* __restrict__ rt, const float* __restrict__ rc,
                            const float* __restrict__ rp, __half* __restrict__ out)
{
    int idx = blockIdx.x * blockDim.x + threadIdx.x;
    int row = idx / 384, c4 = idx % 384;
    const float* srcs[3] = {rt, rc, rp};
    const float* s = srcs[c4 >> 7];
    int c = (c4 & 127) * 4;
    float4 t = *(const float4*)(s + (size_t)row*512 + c);
    ((__half2*)out)[idx*2]   = __floats2half2_rn(t.x, t.y);
    ((__half2*)out)[idx*2+1] = __floats2half2_rn(t.z, t.w);
}

// ---------------- build stacked W half (1536 x 2048) --------------------------------
__global__ void wall_kernel(const float* __restrict__ wkt, const float* __restrict__ wkc,
                            const float* __restrict__ wkp, __half* __restrict__ out)
{
    int idx = blockIdx.x * blockDim.x + threadIdx.x;
    int k = idx >> 9;
    int col4 = idx & 511;
    int l = col4 >> 7, c = (col4 & 127) * 4;
    const float* srcs[3] = {wkt, wkc, wkp};
    const float* s = srcs[k >> 9];
    int kk = k & 511;
    float4 t = *(const float4*)(s + ((size_t)l*512 + kk) * 512 + c);
    ((__half2*)out)[idx*2]   = __floats2half2_rn(t.x, t.y);
    ((__half2*)out)[idx*2+1] = __floats2half2_rn(t.z, t.w);
}

// ---------------- all-layers Wsr -> kw rows [1024,2048), /3 -------------------------
__global__ void wsr_all_kernel(const float* __restrict__ wsall, __half* __restrict__ kw)
{
    int idx = blockIdx.x * blockDim.x + threadIdx.x;  // 4*B*H*N*(DH/4)
    int d4 = idx & 15;
    int n = (idx >> 4) & (Nc - 1);
    int h = (idx >> 14) & 7;
    int b = (idx >> 17) & 1;
    int l = idx >> 18;
    int bh = b * Hc + h;
    float4 t = *(const float4*)(wsall + ((size_t)(b*Nc + n)) * 2048 + l*512 + h*64 + d4*4);
    size_t kd = ((size_t)l * BHc * 2 * Nc + (size_t)bh * 2 * Nc + Nc + n) * DHc + d4*4;
    ((__half2*)(kw + kd))[0] = __floats2half2_rn(t.x*(1.f/3.f), t.y*(1.f/3.f));
    ((__half2*)(kw + kd))[1] = __floats2half2_rn(t.z*(1.f/3.f), t.w*(1.f/3.f));
}

// ---------------- fused combine + rel_shift + softmax over heads (fp16 scores) ------
__global__ void softmax_fused_kernel(const __half* __restrict__ sc,
                                     __half* __restrict__ attn,
                                     float* __restrict__ attn_raw)
{
    int t = blockIdx.x * blockDim.x + threadIdx.x;   // B*N*(N/4)
    int j4 = (t & 255) * 4;
    int i = (t >> 8) & (Nc - 1);
    int b = t >> 18;
    size_t scb = ((size_t)(b * Hc)) << 21;           // bh stride = 1024*2048 = 2^21
    float d[Hc][4];
#pragma unroll
    for (int h = 0; h < Hc; h++) {
        const __half2* p = (const __half2*)(sc + scb + ((size_t)h << 21) + (size_t)i * 2048 + j4);
        float2 a0 = __half22float2(p[0]);
        float2 a1 = __half22float2(p[1]);
        d[h][0] = a0.x; d[h][1] = a0.y; d[h][2] = a1.x; d[h][3] = a1.y;
    }
#pragma unroll
    for (int e = 0; e < 4; e++) {
        int j = j4 + e;
        int f = i * Nc + j + Nc;
        int i2 = f / (Nc + 1);
        int jj = f - i2 * (Nc + 1);
        if (jj != 0) {
            size_t bd = scb + (size_t)i2 * 2048 + Nc + (jj - 1);
#pragma unroll
            for (int h = 0; h < Hc; h++)
                d[h][e] = (d[h][e] + __half2float(sc[bd + ((size_t)h << 21)])) * SCALEc;
        } else {
#pragma unroll
            for (int h = 0; h < Hc; h++) d[h][e] *= SCALEc;
        }
    }
#pragma unroll
    for (int e = 0; e < 4; e++) {
        float m = d[0][e];
#pragma unroll
        for (int h = 1; h < Hc; h++) m = fmaxf(m, d[h][e]);
        float s = 0.f;
#pragma unroll
        for (int h = 0; h < Hc; h++) { d[h][e] = expf(d[h][e] - m); s += d[h][e]; }
        float inv = 1.f / s;
#pragma unroll
        for (int h = 0; h < Hc; h++) d[h][e] *= inv;
    }
    size_t abase = (((size_t)(b * Hc)) << 20) + (size_t)i * Nc + j4;
#pragma unroll
    for (int h = 0; h < Hc; h++) {
        size_t o = abase + ((size_t)h << 20);
        if (attn_raw) {
            float4 r; r.x = d[h][0]; r.y = d[h][1]; r.z = d[h][2]; r.w = d[h][3];
            *(float4*)(attn_raw + o) = r;
        }
        ((__half2*)(attn + o))[0] = __floats2half2_rn(d[h][0], d[h][1]);
        ((__half2*)(attn + o))[1] = __floats2half2_rn(d[h][2], d[h][3]);
    }
}

// ===================================================================================
extern "C" void kernel_launch(void* const* d_in, const int* in_sizes, int n_in,
                              void* d_out, int out_size)
{
    const float* x_in    = (const float*)d_in[0];
    const float* r_t     = (const float*)d_in[1];
    const float* r_c     = (const float*)d_in[2];
    const float* r_p     = (const float*)d_in[3];
    const float* bias_pf = (const float*)d_in[4];
    const float* ln1_g   = (const float*)d_in[5];
    const float* ln1_b   = (const float*)d_in[6];
    const float* w_qkv   = (const float*)d_in[7];
    const float* w_out   = (const float*)d_in[8];
    const float* b_out   = (const float*)d_in[9];
    const float* w_kt    = (const float*)d_in[10];
    const float* w_kc    = (const float*)d_in[11];
    const float* w_kp    = (const float*)d_in[12];
    const float* ln2_g   = (const float*)d_in[13];
    const float* ln2_b   = (const float*)d_in[14];
    const float* w_ff1   = (const float*)d_in[15];
    const float* b_ff1   = (const float*)d_in[16];
    const float* w_ff2   = (const float*)d_in[17];
    const float* b_ff2   = (const float*)d_in[18];
    float* out = (float*)d_out;

    __half *xn, *q, *kw, *v, *rcat, *wall, *sc, *attnb, *av, *h1,
           *wqkvh, *wouth, *wff1h, *wff2h;
    float *wsall, *x, *xmid;
    cudaGetSymbolAddress((void**)&xn, g_xn);
    cudaGetSymbolAddress((void**)&q, g_q);
    cudaGetSymbolAddress((void**)&kw, g_kw);
    cudaGetSymbolAddress((void**)&v, g_v);
    cudaGetSymbolAddress((void**)&rcat, g_rcat);
    cudaGetSymbolAddress((void**)&wall, g_wall);
    cudaGetSymbolAddress((void**)&wsall, g_wsall);
    cudaGetSymbolAddress((void**)&sc, g_sc);
    cudaGetSymbolAddress((void**)&attnb, g_attn);
    cudaGetSymbolAddress((void**)&av, g_av);
    cudaGetSymbolAddress((void**)&h1, g_h1);
    cudaGetSymbolAddress((void**)&x, g_x);
    cudaGetSymbolAddress((void**)&xmid, g_xmid);
    cudaGetSymbolAddress((void**)&wqkvh, g_wqkvh);
    cudaGetSymbolAddress((void**)&wouth, g_wouth);
    cudaGetSymbolAddress((void**)&wff1h, g_wff1h);
    cudaGetSymbolAddress((void**)&wff2h, g_wff2h);

    float* x_out    = out;
    float* attn_out = out + (size_t)Mc * Dc;

    // ---- upfront (single stream): weights + relative-projection chain --------------
    whall_kernel<<<(4*Dc*3*HDc/4 + 4*HDc*Dc/4 + 4*Dc*FFc/4 + 4*FFc*Dc/4)/256, 256>>>(
        w_qkv, w_out, w_ff1, w_ff2, wqkvh, wouth, wff1h, wff2h);
    rcat_kernel<<<(Mc*3*Dc/4)/256, 256>>>(r_t, r_c, r_p, rcat);
    wall_kernel<<<(3*Dc*2048/4)/256, 256>>>(w_kt, w_kc, w_kp, wall);
    h_gemm<128,128,64,32,false,float,3><<<dim3(16,16), 256>>>(
        rcat, wall, wsall, 3*Dc, 3*Dc, 2048, 2048, 0,0,0,
        nullptr, nullptr, nullptr, nullptr, 0);
    wsr_all_kernel<<<(4*BHc*Nc*DHc/4)/256, 256>>>(wsall, kw);

    const float* cur = x_in;
    for (int l = 0; l < 4; l++) {
        __half* kw_l = kw + (size_t)l * BHc * 2 * Nc * DHc;
        ln_kernel<<<Mc, 128>>>(cur, xn, ln1_g + l*Dc, ln1_b + l*Dc);
        // qkv GEMM with scatter epilogue: q(+bias_pf), kw K-half, v directly
        h_gemm<128,128,64,32,false,__half,3><<<dim3(12,16), 256>>>(
            xn, wqkvh + (size_t)l*Dc*3*HDc, q, Dc, Dc, 3*HDc, 3*HDc, 0,0,0,
            bias_pf, nullptr, kw_l, v, 5);
        // combined scores: [AC | BDraw] in one GEMM, N=2048 per bh, fp16 out
        h_gemm<128,128,64,32,true,__half,3><<<dim3(16,8,BHc), 256>>>(
            q, kw_l, sc, DHc, DHc, DHc, 2*Nc,
            (long long)Nc*DHc, (long long)2*Nc*DHc, (long long)Nc*2*Nc,
            nullptr, nullptr, nullptr, nullptr, 0);
        softmax_fused_kernel<<<(int)(((size_t)Bc*Nc*Nc/4)/256), 256>>>(
            sc, attnb, (l == 3) ? attn_out : nullptr);
        h_gemm<64,64,32,16,false,__half,4><<<dim3(1,16,BHc), 256>>>(
            attnb, v, av, Nc, Nc, DHc, HDc,
            (long long)Nc*Nc, (long long)Nc*DHc, 0,
            nullptr, nullptr, nullptr, nullptr, 4);
        h_gemm<64,64,32,16,false,float,4><<<dim3(8,32), 256>>>(
            av, wouth + (size_t)l*HDc*Dc, xmid, HDc, HDc, Dc, Dc,
            0,0,0, b_out + l*Dc, cur, nullptr, nullptr, 2);
        ln_kernel<<<Mc, 128>>>(xmid, xn, ln2_g + l*Dc, ln2_b + l*Dc);
        h_gemm<128,128,64,32,false,__half,3><<<dim3(16,16), 256>>>(
            xn, wff1h + (size_t)l*Dc*FFc, h1, Dc, Dc, FFc, FFc,
            0,0,0, b_ff1 + l*FFc, nullptr, nullptr, nullptr, 3);
        float* xdst = (l == 3) ? x_out : x;
        h_gemm<64,64,32,16,false,float,4><<<dim3(8,32), 256>>>(
            h1, wff2h + (size_t)l*FFc*Dc, xdst, FFc, FFc, Dc, Dc,
            0,0,0, b_ff2 + l*Dc, xmid, nullptr, nullptr, 2);
        cur = x;
    }
}